// round 8
// baseline (speedup 1.0000x reference)
#include <cuda_runtime.h>
#include <math.h>
#include <float.h>

#define BS 16
#define CH 64
#define NC 81
#define HW 65536          // 256*256
#define FG_STCH 1
#define JCNT (CH - FG_STCH)            // 63
#define SPLIT 4                        // chunks per (b,c) row
#define CHUNK (HW / 4 / SPLIT)         // float4 per chunk = 4096
#define NBLK (BS * CH * SPLIT)         // 4096 streaming blocks
#define NITEMS (BS * JCNT)             // 1008
#define NLOSS_BLK 126                  // 8 items/block (warp-per-item)
#define WPB 8

// Scratch (no cudaMalloc allowed)
__device__ float g_maxprob_part[NBLK];
__device__ float g_partial[NLOSS_BLK * 3];
__device__ int   g_loss_count;         // loss block completions; reset by last block
__device__ float g_prefetch_sink[8];   // dummy sink so prefetch isn't DCE'd

// ---------------------------------------------------------------------------
// Kernel A: 4096 streaming blocks (64KB chunk each, evict-first loads) plus
// ONE prefetch block (blk == NBLK) that pulls all loss-kernel inputs into L2
// with normal caching loads. Streaming data uses __ldcs so the prefetched
// lines survive until the loss kernel runs.
// ---------------------------------------------------------------------------
__global__ __launch_bounds__(256) void maxprob_kernel(
    const float4* __restrict__ p,
    const float4* __restrict__ cls_logits4,   // 82944 floats = 20736 float4
    const float4* __restrict__ small4,        // iou_scores..rand_vals swept per-array
    const float*  __restrict__ iou_scores,
    const int*    __restrict__ target_ids,
    const int*    __restrict__ map_indices,
    const float*  __restrict__ map_ious,
    const float*  __restrict__ rand_vals)
{
    const int blk = blockIdx.x;

    if (blk == NBLK) {
        // ----- prefetch block: touch every loss input line with __ldcg -----
        float acc = 0.0f;
        // cls_logits: 20736 float4 -> 81 per thread
        for (int i = threadIdx.x; i < (BS * CH * NC) / 4; i += 256) {
            float4 v = __ldcg(&cls_logits4[i]);
            acc += v.x + v.y + v.z + v.w;
        }
        // small arrays: BS*CH = 1024 elems each
        for (int i = threadIdx.x; i < BS * CH; i += 256) {
            acc += __ldcg(&iou_scores[i]);
            acc += (float)__ldcg(&target_ids[i]);
            acc += __ldcg(&map_ious[i]);
            acc += __ldcg(&rand_vals[i]);
        }
        for (int i = threadIdx.x; i < BS * 2 * CH; i += 256) {
            acc += (float)__ldcg(&map_indices[i]);
        }
        (void)small4;
        // reduce + write to sink (prevents dead-code elimination)
#pragma unroll
        for (int o = 16; o > 0; o >>= 1)
            acc += __shfl_xor_sync(0xFFFFFFFFu, acc, o);
        if ((threadIdx.x & 31) == 0)
            g_prefetch_sink[threadIdx.x >> 5] = acc;
        return;
    }

    // ----- streaming chunk (unchanged, proven ~6.8 TB/s) -----
    const float4* base = p + (size_t)blk * CHUNK;
    float m0 = -FLT_MAX, m1 = -FLT_MAX, m2 = -FLT_MAX, m3 = -FLT_MAX;
#pragma unroll
    for (int i = 0; i < CHUNK / (256 * 4); i++) {
        const int bi = i * 256 * 4 + threadIdx.x;
        float4 v0 = __ldcs(&base[bi]);
        float4 v1 = __ldcs(&base[bi + 256]);
        float4 v2 = __ldcs(&base[bi + 512]);
        float4 v3 = __ldcs(&base[bi + 768]);
        m0 = fmaxf(m0, fmaxf(fmaxf(v0.x, v0.y), fmaxf(v0.z, v0.w)));
        m1 = fmaxf(m1, fmaxf(fmaxf(v1.x, v1.y), fmaxf(v1.z, v1.w)));
        m2 = fmaxf(m2, fmaxf(fmaxf(v2.x, v2.y), fmaxf(v2.z, v2.w)));
        m3 = fmaxf(m3, fmaxf(fmaxf(v3.x, v3.y), fmaxf(v3.z, v3.w)));
    }
    float m = fmaxf(fmaxf(m0, m1), fmaxf(m2, m3));

#pragma unroll
    for (int o = 16; o > 0; o >>= 1)
        m = fmaxf(m, __shfl_xor_sync(0xFFFFFFFFu, m, o));

    __shared__ float sm[8];
    if ((threadIdx.x & 31) == 0) sm[threadIdx.x >> 5] = m;
    __syncthreads();
    if (threadIdx.x < 8) {
        m = sm[threadIdx.x];
#pragma unroll
        for (int o = 4; o > 0; o >>= 1)
            m = fmaxf(m, __shfl_xor_sync(0xFFu, m, o));
        if (threadIdx.x == 0) g_maxprob_part[blk] = m;
    }
}

// ---------------------------------------------------------------------------
// Kernel B: full loss, 126 blocks x 256 threads, warp-per-item. All input
// lines are L2-resident thanks to the prefetch block. Last block finalizes.
// ---------------------------------------------------------------------------
__global__ __launch_bounds__(256) void loss_kernel(
    const float* __restrict__ cls_logits,   // (bs, ch, C)
    const float* __restrict__ iou_scores,   // (bs, ch, 1)
    const int*   __restrict__ target_ids,   // (bs, ch)
    const int*   __restrict__ map_indices,  // (bs, 2, ch)
    const float* __restrict__ map_ious,     // (bs, ch)
    const float* __restrict__ rand_vals,    // (bs, ch)
    float* __restrict__ out)                // [iou_loss, cls_loss]
{
    const int warp = threadIdx.x >> 5;      // 0..7
    const int lane = threadIdx.x & 31;
    const int item = blockIdx.x * WPB + warp;   // 0..1007 exact

    const int b = item / JCNT;
    const int j = FG_STCH + (item % JCNT);

    // wave 1: independent loads (L2 hits after prefetch)
    const int   pj  = __ldg(&map_indices[b * 2 * CH + j]);
    const int   gj  = __ldg(&map_indices[b * 2 * CH + CH + j]);
    const float iou = __ldg(&map_ious[b * CH + j]);
    const float rnd = __ldg(&rand_vals[b * CH + j]);

    // wave 2: dependent gathers (L2 hits)
    const int   tid       = __ldg(&target_ids[b * CH + gj]);
    const float preds_iou = __ldg(&iou_scores[b * CH + pj]);
    const float* row = cls_logits + (size_t)(b * CH + pj) * NC;
    const float x0 = __ldg(&row[lane]);
    const float x1 = __ldg(&row[lane + 32]);
    const float x2 = (lane < NC - 64) ? __ldg(&row[lane + 64]) : -FLT_MAX;
    const float* mpp = &g_maxprob_part[(b * CH + pj) * SPLIT];
    const float mpa = mpp[0], mpb = mpp[1], mpc = mpp[2], mpd = mpp[3];

    // arithmetic
    const int cls = max(0, tid - FG_STCH + 1);
    const float mp = fmaxf(fmaxf(mpa, mpb), fmaxf(mpc, mpd));
    const bool remove = (mp < 0.1f) && (rnd < 0.9f);
    const float wght = remove ? 0.0f : ((iou < 0.2f) ? 1.0f : 2.0f);

    const float y = fabsf(preds_iou - iou);
    const float iou_el = (y < 0.1f) ? (y * y * 5.0f) : (y - 0.05f);

    // warp-parallel log-softmax over C=81
    float mx = fmaxf(fmaxf(x0, x1), x2);
#pragma unroll
    for (int o = 16; o > 0; o >>= 1)
        mx = fmaxf(mx, __shfl_xor_sync(0xFFFFFFFFu, mx, o));

    float s = expf(x0 - mx) + expf(x1 - mx);
    if (lane < NC - 64) s += expf(x2 - mx);
#pragma unroll
    for (int o = 16; o > 0; o >>= 1)
        s += __shfl_xor_sync(0xFFFFFFFFu, s, o);

    float v0 = 0.0f, v1 = 0.0f, v2 = 0.0f;
    if (lane == 0) {
        const float ce = -(__ldg(&row[cls]) - mx - logf(s));  // w[cls]==1
        v0 = wght;
        v1 = iou_el * wght;
        v2 = ce * wght;
    }

    // block reduce across 8 warps
    __shared__ float s0[WPB], s1[WPB], s2[WPB];
    if (lane == 0) { s0[warp] = v0; s1[warp] = v1; s2[warp] = v2; }
    __syncthreads();

    __shared__ bool is_last;
    if (warp == 0) {
        float a0 = (lane < WPB) ? s0[lane] : 0.0f;
        float a1 = (lane < WPB) ? s1[lane] : 0.0f;
        float a2 = (lane < WPB) ? s2[lane] : 0.0f;
#pragma unroll
        for (int o = WPB / 2; o > 0; o >>= 1) {
            a0 += __shfl_xor_sync(0xFFFFFFFFu, a0, o);
            a1 += __shfl_xor_sync(0xFFFFFFFFu, a1, o);
            a2 += __shfl_xor_sync(0xFFFFFFFFu, a2, o);
        }
        if (lane == 0) {
            g_partial[blockIdx.x * 3 + 0] = a0;
            g_partial[blockIdx.x * 3 + 1] = a1;
            g_partial[blockIdx.x * 3 + 2] = a2;
            __threadfence();
            const int prev = atomicAdd(&g_loss_count, 1);
            is_last = (prev == NLOSS_BLK - 1);
        }
        __syncwarp();

        if (is_last) {
            float b0 = 0.0f, b1 = 0.0f, b2 = 0.0f;
#pragma unroll
            for (int k = 0; k < 4; k++) {
                const int i = lane + 32 * k;
                if (i < NLOSS_BLK) {
                    b0 += __ldcg(&g_partial[i * 3 + 0]);
                    b1 += __ldcg(&g_partial[i * 3 + 1]);
                    b2 += __ldcg(&g_partial[i * 3 + 2]);
                }
            }
#pragma unroll
            for (int o = 16; o > 0; o >>= 1) {
                b0 += __shfl_xor_sync(0xFFFFFFFFu, b0, o);
                b1 += __shfl_xor_sync(0xFFFFFFFFu, b1, o);
                b2 += __shfl_xor_sync(0xFFFFFFFFu, b2, o);
            }
            if (lane == 0) {
                const float wsum = b0 + 0.0001f;
                out[0] = b1 / wsum;   // iou_loss
                out[1] = b2 / wsum;   // cls_loss
                g_loss_count = 0;     // reset for next graph replay
            }
        }
    }
}

// ---------------------------------------------------------------------------
extern "C" void kernel_launch(void* const* d_in, const int* in_sizes, int n_in,
                              void* d_out, int out_size) {
    const float* cls_logits     = (const float*)d_in[0];
    const float* iou_scores     = (const float*)d_in[1];
    const int*   target_ids     = (const int*)  d_in[2];
    const int*   map_indices    = (const int*)  d_in[3];
    const float* map_ious       = (const float*)d_in[4];
    const float* pred_mask_prob = (const float*)d_in[5];
    const float* rand_vals      = (const float*)d_in[6];
    float* out = (float*)d_out;

    maxprob_kernel<<<NBLK + 1, 256>>>((const float4*)pred_mask_prob,
                                      (const float4*)cls_logits,
                                      (const float4*)iou_scores,
                                      iou_scores, target_ids, map_indices,
                                      map_ious, rand_vals);
    loss_kernel<<<NLOSS_BLK, 256>>>(cls_logits, iou_scores, target_ids,
                                    map_indices, map_ious, rand_vals, out);
}

// round 9
// speedup vs baseline: 1.0901x; 1.0901x over previous
#include <cuda_runtime.h>
#include <math.h>
#include <float.h>

#define BS 16
#define CH 64
#define NC 81
#define HW 65536          // 256*256
#define FG_STCH 1
#define JCNT (CH - FG_STCH)            // 63
#define SPLIT 4                        // chunks per (b,c) row
#define CHUNK (HW / 4 / SPLIT)         // float4 per chunk = 4096
#define NBLK (BS * CH * SPLIT)         // 4096 streaming blocks
#define NITEMS (BS * JCNT)             // 1008
#define NLOSS_BLK 126                  // 8 items/block (warp-per-item)
#define WPB 8

// Scratch (no cudaMalloc allowed)
__device__ float g_maxprob_part[NBLK];
__device__ float g_partial[NLOSS_BLK * 3];
__device__ int   g_loss_count;         // loss block completions; reset by last block

// ---------------------------------------------------------------------------
// Kernel A (identical to the proven R7 streaming kernel, no prefetch block):
// partial max over one 64KB chunk per block, evict-first loads. ~6.9 TB/s.
// ---------------------------------------------------------------------------
__global__ __launch_bounds__(256) void maxprob_kernel(const float4* __restrict__ p) {
    const int blk = blockIdx.x;                    // 0..4095
    const float4* base = p + (size_t)blk * CHUNK;

    float m0 = -FLT_MAX, m1 = -FLT_MAX, m2 = -FLT_MAX, m3 = -FLT_MAX;
#pragma unroll
    for (int i = 0; i < CHUNK / (256 * 4); i++) {
        const int bi = i * 256 * 4 + threadIdx.x;
        float4 v0 = __ldcs(&base[bi]);
        float4 v1 = __ldcs(&base[bi + 256]);
        float4 v2 = __ldcs(&base[bi + 512]);
        float4 v3 = __ldcs(&base[bi + 768]);
        m0 = fmaxf(m0, fmaxf(fmaxf(v0.x, v0.y), fmaxf(v0.z, v0.w)));
        m1 = fmaxf(m1, fmaxf(fmaxf(v1.x, v1.y), fmaxf(v1.z, v1.w)));
        m2 = fmaxf(m2, fmaxf(fmaxf(v2.x, v2.y), fmaxf(v2.z, v2.w)));
        m3 = fmaxf(m3, fmaxf(fmaxf(v3.x, v3.y), fmaxf(v3.z, v3.w)));
    }
    float m = fmaxf(fmaxf(m0, m1), fmaxf(m2, m3));

#pragma unroll
    for (int o = 16; o > 0; o >>= 1)
        m = fmaxf(m, __shfl_xor_sync(0xFFFFFFFFu, m, o));

    __shared__ float sm[8];
    if ((threadIdx.x & 31) == 0) sm[threadIdx.x >> 5] = m;
    __syncthreads();
    if (threadIdx.x < 8) {
        m = sm[threadIdx.x];
#pragma unroll
        for (int o = 4; o > 0; o >>= 1)
            m = fmaxf(m, __shfl_xor_sync(0xFFu, m, o));
        if (threadIdx.x == 0) g_maxprob_part[blk] = m;
    }
}

// ---------------------------------------------------------------------------
// Kernel B: launched with Programmatic Stream Serialization. Blocks get SM
// slots during maxprob's drain tail; the maxprob-independent pre-work
// (gathers, softmax/CE, smooth-L1) overlaps the tail, then
// cudaGridDependencySynchronize() waits for maxprob's completion before
// reading g_maxprob_part.
// ---------------------------------------------------------------------------
__global__ __launch_bounds__(256) void loss_kernel(
    const float* __restrict__ cls_logits,   // (bs, ch, C)
    const float* __restrict__ iou_scores,   // (bs, ch, 1)
    const int*   __restrict__ target_ids,   // (bs, ch)
    const int*   __restrict__ map_indices,  // (bs, 2, ch)
    const float* __restrict__ map_ious,     // (bs, ch)
    const float* __restrict__ rand_vals,    // (bs, ch)
    float* __restrict__ out)                // [iou_loss, cls_loss]
{
    const int warp = threadIdx.x >> 5;      // 0..7
    const int lane = threadIdx.x & 31;
    const int item = blockIdx.x * WPB + warp;   // 0..1007 exact

    const int b = item / JCNT;
    const int j = FG_STCH + (item % JCNT);

    // ---- pre-work: everything independent of maxprob ----
    const int   pj  = __ldg(&map_indices[b * 2 * CH + j]);
    const int   gj  = __ldg(&map_indices[b * 2 * CH + CH + j]);
    const float iou = __ldg(&map_ious[b * CH + j]);
    const float rnd = __ldg(&rand_vals[b * CH + j]);

    const int   tid       = __ldg(&target_ids[b * CH + gj]);
    const float preds_iou = __ldg(&iou_scores[b * CH + pj]);
    const float* row = cls_logits + (size_t)(b * CH + pj) * NC;
    const float x0 = __ldg(&row[lane]);
    const float x1 = __ldg(&row[lane + 32]);
    const float x2 = (lane < NC - 64) ? __ldg(&row[lane + 64]) : -FLT_MAX;

    const int cls = max(0, tid - FG_STCH + 1);
    const float wght_base = (iou < 0.2f) ? 1.0f : 2.0f;
    const bool  rnd_rm = (rnd < 0.9f);

    const float y = fabsf(preds_iou - iou);
    const float iou_el = (y < 0.1f) ? (y * y * 5.0f) : (y - 0.05f);

    // warp-parallel log-softmax over C=81
    float mx = fmaxf(fmaxf(x0, x1), x2);
#pragma unroll
    for (int o = 16; o > 0; o >>= 1)
        mx = fmaxf(mx, __shfl_xor_sync(0xFFFFFFFFu, mx, o));

    float s = expf(x0 - mx) + expf(x1 - mx);
    if (lane < NC - 64) s += expf(x2 - mx);
#pragma unroll
    for (int o = 16; o > 0; o >>= 1)
        s += __shfl_xor_sync(0xFFFFFFFFu, s, o);

    float ce = 0.0f;
    if (lane == 0)
        ce = -(__ldg(&row[cls]) - mx - logf(s));   // w[cls]==1

    // ---- wait for maxprob kernel's writes to be visible ----
    cudaGridDependencySynchronize();

    float v0 = 0.0f, v1 = 0.0f, v2 = 0.0f;
    if (lane == 0) {
        const float* mpp = &g_maxprob_part[(b * CH + pj) * SPLIT];
        const float mp = fmaxf(fmaxf(mpp[0], mpp[1]), fmaxf(mpp[2], mpp[3]));
        const bool remove = (mp < 0.1f) && rnd_rm;
        const float wght = remove ? 0.0f : wght_base;
        v0 = wght;
        v1 = iou_el * wght;
        v2 = ce * wght;
    }

    // block reduce across 8 warps
    __shared__ float s0[WPB], s1[WPB], s2[WPB];
    if (lane == 0) { s0[warp] = v0; s1[warp] = v1; s2[warp] = v2; }
    __syncthreads();

    __shared__ bool is_last;
    if (warp == 0) {
        float a0 = (lane < WPB) ? s0[lane] : 0.0f;
        float a1 = (lane < WPB) ? s1[lane] : 0.0f;
        float a2 = (lane < WPB) ? s2[lane] : 0.0f;
#pragma unroll
        for (int o = WPB / 2; o > 0; o >>= 1) {
            a0 += __shfl_xor_sync(0xFFFFFFFFu, a0, o);
            a1 += __shfl_xor_sync(0xFFFFFFFFu, a1, o);
            a2 += __shfl_xor_sync(0xFFFFFFFFu, a2, o);
        }
        if (lane == 0) {
            g_partial[blockIdx.x * 3 + 0] = a0;
            g_partial[blockIdx.x * 3 + 1] = a1;
            g_partial[blockIdx.x * 3 + 2] = a2;
            __threadfence();
            const int prev = atomicAdd(&g_loss_count, 1);
            is_last = (prev == NLOSS_BLK - 1);
        }
        __syncwarp();

        // last block: deterministic fixed-order final reduction (L2-warm)
        if (is_last) {
            float b0 = 0.0f, b1 = 0.0f, b2 = 0.0f;
#pragma unroll
            for (int k = 0; k < 4; k++) {
                const int i = lane + 32 * k;
                if (i < NLOSS_BLK) {
                    b0 += __ldcg(&g_partial[i * 3 + 0]);
                    b1 += __ldcg(&g_partial[i * 3 + 1]);
                    b2 += __ldcg(&g_partial[i * 3 + 2]);
                }
            }
#pragma unroll
            for (int o = 16; o > 0; o >>= 1) {
                b0 += __shfl_xor_sync(0xFFFFFFFFu, b0, o);
                b1 += __shfl_xor_sync(0xFFFFFFFFu, b1, o);
                b2 += __shfl_xor_sync(0xFFFFFFFFu, b2, o);
            }
            if (lane == 0) {
                const float wsum = b0 + 0.0001f;
                out[0] = b1 / wsum;   // iou_loss
                out[1] = b2 / wsum;   // cls_loss
                g_loss_count = 0;     // reset for next graph replay
            }
        }
    }
}

// ---------------------------------------------------------------------------
extern "C" void kernel_launch(void* const* d_in, const int* in_sizes, int n_in,
                              void* d_out, int out_size) {
    const float* cls_logits     = (const float*)d_in[0];
    const float* iou_scores     = (const float*)d_in[1];
    const int*   target_ids     = (const int*)  d_in[2];
    const int*   map_indices    = (const int*)  d_in[3];
    const float* map_ious       = (const float*)d_in[4];
    const float* pred_mask_prob = (const float*)d_in[5];
    const float* rand_vals      = (const float*)d_in[6];
    float* out = (float*)d_out;

    maxprob_kernel<<<NBLK, 256>>>((const float4*)pred_mask_prob);

    // Launch loss_kernel with Programmatic Stream Serialization so its blocks
    // can be scheduled into maxprob's drain tail; the device-side
    // cudaGridDependencySynchronize() enforces correctness.
    cudaLaunchConfig_t cfg = {};
    cfg.gridDim  = dim3(NLOSS_BLK, 1, 1);
    cfg.blockDim = dim3(256, 1, 1);
    cfg.dynamicSmemBytes = 0;
    cfg.stream = 0;   // legacy default stream (same as <<<>>> above)
    cudaLaunchAttribute attrs[1];
    attrs[0].id = cudaLaunchAttributeProgrammaticStreamSerialization;
    attrs[0].val.programmaticStreamSerializationAllowed = 1;
    cfg.attrs = attrs;
    cfg.numAttrs = 1;

    cudaLaunchKernelEx(&cfg, loss_kernel,
                       cls_logits, iou_scores, target_ids,
                       map_indices, map_ious, rand_vals, out);
}

// round 10
// speedup vs baseline: 5.7565x; 5.2804x over previous
#include <cuda_runtime.h>
#include <math.h>
#include <float.h>

#define BS 16
#define CH 64
#define NC 81
#define HW 65536          // 256*256
#define FG_STCH 1
#define JCNT (CH - FG_STCH)            // 63
#define NITEMS (BS * JCNT)             // 1008
#define NLOSS_BLK 126                  // 8 items/block (warp-per-item)
#define WPB 8
#define SCAN_THREADS 256
#define ITERS (HW / 4 / SCAN_THREADS)  // 64 float4-iterations per (b,c)

// Scratch (no cudaMalloc allowed)
__device__ int   g_ge_thr[BS * CH];    // 1 iff any pred_mask_prob[b,c,:] >= 0.1
__device__ float g_partial[NLOSS_BLK * 3];
__device__ int   g_loss_count;         // reset by last block each call

// ---------------------------------------------------------------------------
// Kernel A: early-exit threshold scan. The reference only ever uses
// max_prob via (max < 0.1), so we compute the exact boolean
// "exists element >= 0.1" and stop at the first witness. Expected cost for
// non-degenerate data: ONE 4KB tile per (b,c). Worst case: full scan
// (identical result to computing the true max and thresholding).
// ---------------------------------------------------------------------------
__global__ __launch_bounds__(SCAN_THREADS) void scan_kernel(const float4* __restrict__ p) {
    const int bc = blockIdx.x;                      // 0..1023
    const float4* base = p + (size_t)bc * (HW / 4);

    int found = 0;
    for (int i = 0; i < ITERS; i++) {
        const float4 v = __ldcs(&base[i * SCAN_THREADS + threadIdx.x]);
        const float m = fmaxf(fmaxf(v.x, v.y), fmaxf(v.z, v.w));
        found = (m >= 0.1f);
        if (__syncthreads_or(found)) { found = 1; break; }
    }
    // After early exit, 'found' is 1 on all threads (set in the break path
    // via the syncthreads_or result); after a full scan it is this thread's
    // last-tile predicate — reduce across the block once more for that case.
    const int any = __syncthreads_or(found);
    if (threadIdx.x == 0) g_ge_thr[bc] = any;
}

// ---------------------------------------------------------------------------
// Kernel B: full loss, 126 blocks x 256 threads, warp-per-item.
// row[cls] fetched via warp shuffle from the softmax registers (no third
// dependent load). Last block performs the final reduction inline.
// ---------------------------------------------------------------------------
__global__ __launch_bounds__(256) void loss_kernel(
    const float* __restrict__ cls_logits,   // (bs, ch, C)
    const float* __restrict__ iou_scores,   // (bs, ch, 1)
    const int*   __restrict__ target_ids,   // (bs, ch)
    const int*   __restrict__ map_indices,  // (bs, 2, ch)
    const float* __restrict__ map_ious,     // (bs, ch)
    const float* __restrict__ rand_vals,    // (bs, ch)
    float* __restrict__ out)                // [iou_loss, cls_loss]
{
    const int warp = threadIdx.x >> 5;      // 0..7
    const int lane = threadIdx.x & 31;
    const int item = blockIdx.x * WPB + warp;   // 0..1007 exact

    const int b = item / JCNT;
    const int j = FG_STCH + (item % JCNT);

    // wave 1: independent loads
    const int   pj  = __ldg(&map_indices[b * 2 * CH + j]);
    const int   gj  = __ldg(&map_indices[b * 2 * CH + CH + j]);
    const float iou = __ldg(&map_ious[b * CH + j]);
    const float rnd = __ldg(&rand_vals[b * CH + j]);

    // wave 2: dependent gathers
    const int   tid       = __ldg(&target_ids[b * CH + gj]);
    const float preds_iou = __ldg(&iou_scores[b * CH + pj]);
    const int   ge_thr    = g_ge_thr[b * CH + pj];      // L2-warm from kernel A
    const float* row = cls_logits + (size_t)(b * CH + pj) * NC;
    const float x0 = __ldg(&row[lane]);
    const float x1 = __ldg(&row[lane + 32]);
    const float x2 = (lane < NC - 64) ? __ldg(&row[lane + 64]) : -FLT_MAX;

    // arithmetic
    const int cls = max(0, tid - FG_STCH + 1);          // warp-uniform
    const bool remove = (!ge_thr) && (rnd < 0.9f);      // == (mp<0.1) && (rnd<0.9)
    const float wght = remove ? 0.0f : ((iou < 0.2f) ? 1.0f : 2.0f);

    const float y = fabsf(preds_iou - iou);
    const float iou_el = (y < 0.1f) ? (y * y * 5.0f) : (y - 0.05f);

    // warp-parallel log-softmax over C=81
    float mx = fmaxf(fmaxf(x0, x1), x2);
#pragma unroll
    for (int o = 16; o > 0; o >>= 1)
        mx = fmaxf(mx, __shfl_xor_sync(0xFFFFFFFFu, mx, o));

    float s = expf(x0 - mx) + expf(x1 - mx);
    if (lane < NC - 64) s += expf(x2 - mx);
#pragma unroll
    for (int o = 16; o > 0; o >>= 1)
        s += __shfl_xor_sync(0xFFFFFFFFu, s, o);

    // row[cls] via shuffle (cls uniform across the warp)
    const float sel = (cls < 32) ? x0 : (cls < 64) ? x1 : x2;
    const float row_cls = __shfl_sync(0xFFFFFFFFu, sel, cls & 31);

    float v0 = 0.0f, v1 = 0.0f, v2 = 0.0f;
    if (lane == 0) {
        const float ce = -(row_cls - mx - logf(s));     // w[cls]==1
        v0 = wght;
        v1 = iou_el * wght;
        v2 = ce * wght;
    }

    // block reduce across 8 warps
    __shared__ float s0[WPB], s1[WPB], s2[WPB];
    if (lane == 0) { s0[warp] = v0; s1[warp] = v1; s2[warp] = v2; }
    __syncthreads();

    __shared__ bool is_last;
    if (warp == 0) {
        float a0 = (lane < WPB) ? s0[lane] : 0.0f;
        float a1 = (lane < WPB) ? s1[lane] : 0.0f;
        float a2 = (lane < WPB) ? s2[lane] : 0.0f;
#pragma unroll
        for (int o = WPB / 2; o > 0; o >>= 1) {
            a0 += __shfl_xor_sync(0xFFFFFFFFu, a0, o);
            a1 += __shfl_xor_sync(0xFFFFFFFFu, a1, o);
            a2 += __shfl_xor_sync(0xFFFFFFFFu, a2, o);
        }
        if (lane == 0) {
            g_partial[blockIdx.x * 3 + 0] = a0;
            g_partial[blockIdx.x * 3 + 1] = a1;
            g_partial[blockIdx.x * 3 + 2] = a2;
            __threadfence();
            const int prev = atomicAdd(&g_loss_count, 1);
            is_last = (prev == NLOSS_BLK - 1);
        }
        __syncwarp();

        // last block: deterministic fixed-order final reduction (L2-warm)
        if (is_last) {
            float b0 = 0.0f, b1 = 0.0f, b2 = 0.0f;
#pragma unroll
            for (int k = 0; k < 4; k++) {
                const int i = lane + 32 * k;
                if (i < NLOSS_BLK) {
                    b0 += __ldcg(&g_partial[i * 3 + 0]);
                    b1 += __ldcg(&g_partial[i * 3 + 1]);
                    b2 += __ldcg(&g_partial[i * 3 + 2]);
                }
            }
#pragma unroll
            for (int o = 16; o > 0; o >>= 1) {
                b0 += __shfl_xor_sync(0xFFFFFFFFu, b0, o);
                b1 += __shfl_xor_sync(0xFFFFFFFFu, b1, o);
                b2 += __shfl_xor_sync(0xFFFFFFFFu, b2, o);
            }
            if (lane == 0) {
                const float wsum = b0 + 0.0001f;
                out[0] = b1 / wsum;   // iou_loss
                out[1] = b2 / wsum;   // cls_loss
                g_loss_count = 0;     // reset for next graph replay
            }
        }
    }
}

// ---------------------------------------------------------------------------
extern "C" void kernel_launch(void* const* d_in, const int* in_sizes, int n_in,
                              void* d_out, int out_size) {
    const float* cls_logits     = (const float*)d_in[0];
    const float* iou_scores     = (const float*)d_in[1];
    const int*   target_ids     = (const int*)  d_in[2];
    const int*   map_indices    = (const int*)  d_in[3];
    const float* map_ious       = (const float*)d_in[4];
    const float* pred_mask_prob = (const float*)d_in[5];
    const float* rand_vals      = (const float*)d_in[6];
    float* out = (float*)d_out;

    scan_kernel<<<BS * CH, SCAN_THREADS>>>((const float4*)pred_mask_prob);
    loss_kernel<<<NLOSS_BLK, 256>>>(cls_logits, iou_scores, target_ids,
                                    map_indices, map_ious, rand_vals, out);
}